// round 13
// baseline (speedup 1.0000x reference)
#include <cuda_runtime.h>
#include <cuda_bf16.h>

#define S 512
#define BB 512
#define T 64

__device__ float g_den[BB];
__device__ float g_num[BB];
__device__ unsigned g_tick = 0;   // wraps via atomicInc; never reset

typedef unsigned long long u64;

__device__ __forceinline__ u64 ffma2(u64 a, u64 b, u64 c) {
    u64 d; asm("fma.rn.f32x2 %0, %1, %2, %3;" : "=l"(d) : "l"(a), "l"(b), "l"(c)); return d;
}
__device__ __forceinline__ u64 fadd2(u64 a, u64 b) {
    u64 d; asm("add.rn.f32x2 %0, %1, %2;" : "=l"(d) : "l"(a), "l"(b)); return d;
}
__device__ __forceinline__ u64 pack2(float x, float y) {
    u64 d; asm("mov.b64 %0, {%1, %2};" : "=l"(d) : "f"(x), "f"(y)); return d;
}
__device__ __forceinline__ float2 unpack2(u64 v) {
    float2 r; asm("mov.b64 {%0, %1}, %2;" : "=f"(r.x), "=f"(r.y) : "l"(v)); return r;
}
__device__ __forceinline__ float wsum(float v) {
#pragma unroll
    for (int o = 16; o; o >>= 1) v += __shfl_xor_sync(0xffffffffu, v, o);
    return v;
}
#define PAIR_BAR(id) asm volatile("bar.sync %0, 64;" :: "r"(id) : "memory")

// ---------------------------------------------------------------------------
// Two warps per batch (pair); each warp owns 32 output states (lane owns one).
// alpha_j = K + log(u_j), K scalar; scale bookkeeping only at chunk starts.
// Rotating 8-slot prefetch: each step does exactly one __expf and one em/mask
// LDG pair (for step s+9), so no bursts sit between barriers. 8 accumulators.
// ---------------------------------------------------------------------------
__global__ void __launch_bounds__(128, 2) crf_fused(
    const float* __restrict__ em,
    const int*   __restrict__ tags,     // int64 downgraded to int32 by harness
    const int*   __restrict__ mask,     // bool widened to int32 by harness
    const float* __restrict__ trans,
    const float* __restrict__ startT,
    const float* __restrict__ endT,
    float* __restrict__ out)
{
    __shared__ __align__(16) float ubuf[2][2][T];   // [pair][buf][state]
    __shared__ float spart[2][2];                   // [pair][half]
    __shared__ double dpart[4];
    __shared__ unsigned is_last;

    const int warp = threadIdx.x >> 5;   // 0..3
    const int pair = warp >> 1;
    const int half = warp & 1;
    const int j    = threadIdx.x & 31;
    const int o    = half * 32 + j;      // owned output state
    const int bid  = pair + 1;           // named barrier id
    const int b    = blockIdx.x * 2 + pair;

    // E column for state o over from-state pairs
    u64 Ecol2[T / 2];
#pragma unroll
    for (int p = 0; p < T / 2; p++) {
        Ecol2[p] = pack2(__expf(trans[(2 * p) * T + o]),
                         __expf(trans[(2 * p + 1) * T + o]));
    }

    const size_t bT     = (size_t)b * T;
    const size_t stride = (size_t)BB * T;

    // ---- init (s = 0) ----
    float u = __expf(startT[o] + em[bT + o]);
    int buf = 0;
    ubuf[pair][0][o] = u;
    float pw = wsum(u);
    if (j == 0) spart[pair][half] = pw;
    PAIR_BAR(bid);

    float U0    = spart[pair][0] + spart[pair][1];
    float scale = __fdividef(1.0f, U0);   // pending, applied at chunk start
    float pend  = __logf(U0);
    float K     = 0.0f;

    // rotating prefetch file: slot r first converted at step s where s&7==r.
    // invariant: slot r holds em/mask for the next step s with s&7==r.
    float xr[8]; int mr[8];
#pragma unroll
    for (int r = 1; r < 8; r++) {
        xr[r] = em[stride * (r + 1) + bT + o];
        mr[r] = mask[(r + 1) * BB + b];
    }
    xr[0] = em[stride * 9 + bT + o];      // em_9 (first slot-0 conversion is s=8)
    mr[0] = mask[9 * BB + b];
    float xe_cur = __expf(em[stride * 1 + bT + o]);
    int   m_cur  = mask[1 * BB + b];

    // 8-accumulator matvec over the current buffer
    auto matvec = [&]() -> float {
        const ulonglong2* up = reinterpret_cast<const ulonglong2*>(ubuf[pair][buf]);
        u64 a0 = 0, a1 = 0, a2 = 0, a3 = 0, a4 = 0, a5 = 0, a6 = 0, a7 = 0;
#pragma unroll
        for (int k = 0; k < 4; k++) {
            ulonglong2 v0 = up[4 * k];
            ulonglong2 v1 = up[4 * k + 1];
            ulonglong2 v2 = up[4 * k + 2];
            ulonglong2 v3 = up[4 * k + 3];
            a0 = ffma2(v0.x, Ecol2[8 * k],     a0);
            a1 = ffma2(v0.y, Ecol2[8 * k + 1], a1);
            a2 = ffma2(v1.x, Ecol2[8 * k + 2], a2);
            a3 = ffma2(v1.y, Ecol2[8 * k + 3], a3);
            a4 = ffma2(v2.x, Ecol2[8 * k + 4], a4);
            a5 = ffma2(v2.y, Ecol2[8 * k + 5], a5);
            a6 = ffma2(v3.x, Ecol2[8 * k + 6], a6);
            a7 = ffma2(v3.y, Ecol2[8 * k + 7], a7);
        }
        u64 s0 = fadd2(fadd2(a0, a1), fadd2(a2, a3));
        u64 s1 = fadd2(fadd2(a4, a5), fadd2(a6, a7));
        float2 tt = unpack2(fadd2(s0, s1));
        return tt.x + tt.y;
    };

    // one scan step; q static under full unroll
    auto step = [&](int s, int q, bool renorm_chunk) {
        float t = matvec();
        float n;
        if (q == 0) {                      // chunk start: apply pending renorm
            n = t * (xe_cur * scale);
            int m = m_cur;
            u     = m ? n : u;
            K    += m ? pend : 0.0f;
            pend  = m ? 0.0f : pend;
            scale = m ? 1.0f : scale;
        } else {
            n = t * xe_cur;
            u = m_cur ? n : u;
        }
        buf ^= 1;
        ubuf[pair][buf][o] = u;
        if (q == 6 && renorm_chunk) {      // publish U from step-7's u
            float w = wsum(u);
            if (j == 0) spart[pair][half] = w;
        }
        // convert next step's em; refill the converted slot with s+9
        {
            const int slot = (q + 1) & 7;
            float xv = xr[slot]; int mv = mr[slot];
            int sr = s + 9; sr = (sr < S) ? sr : (S - 1);
            xr[slot] = em[stride * sr + bT + o];
            mr[slot] = mask[sr * BB + b];
            xe_cur = __expf(xv);
            m_cur  = mv;
        }
        PAIR_BAR(bid);
        if (q == 7 && renorm_chunk) {      // consume after step-8's bar
            float U = spart[pair][0] + spart[pair][1];
            scale *= __fdividef(1.0f, U);
            pend  += __logf(U);
        }
    };

    for (int c = 0; c < 63; c++) {
#pragma unroll
        for (int q = 0; q < 8; q++) step(1 + 8 * c + q, q, true);
    }
#pragma unroll
    for (int q = 0; q < 7; q++) step(505 + q, q, false);   // steps 505..511

    // den = K + pend + log( sum(scale * u * exp(end)) )
    {
        float v = scale * u * __expf(endT[o]);
        float w = wsum(v);
        if (j == 0) spart[pair][half] = w;
        PAIR_BAR(bid);
        if (o == 0) {
            float V = spart[pair][0] + spart[pair][1];
            g_den[b] = K + pend + __logf(V);
        }
    }

    // ---- numerator (warp half==0 of each pair; lane j owns steps 16j..16j+15)
    if (half == 0) {
        int tg[17]; int mk[16];
#pragma unroll
        for (int q = 0; q < 17; q++) {
            int s = 16 * j + q - 1;
            tg[q] = (s >= 0) ? (tags[s * BB + b] & (T - 1)) : 0;
        }
#pragma unroll
        for (int q = 0; q < 16; q++) mk[q] = mask[(16 * j + q) * BB + b];

        float acc = 0.0f;
        int cnt = 0;
#pragma unroll
        for (int q = 0; q < 16; q++) {
            int s = 16 * j + q;
            int t = tg[q + 1];
            cnt += (mk[q] ? 1 : 0);
            float e = em[stride * s + bT + t];
            if (s == 0)       acc += startT[t] + e;
            else if (mk[q])   acc += trans[tg[q] * T + t] + e;
        }
        acc = wsum(acc);
#pragma unroll
        for (int ofs = 16; ofs; ofs >>= 1) cnt += __shfl_xor_sync(0xffffffffu, cnt, ofs);
        if (j == 0) {
            int last = (cnt >= 1) ? (cnt - 1) : 0;
            int lt = tags[last * BB + b] & (T - 1);
            g_num[b] = acc + endT[lt];
        }
    }

    // ---- ticket-elected last block computes the mean ----
    __threadfence();
    __syncthreads();
    if (threadIdx.x == 0) {
        unsigned old;
        asm volatile("atom.global.inc.u32 %0, [%1], %2;"
                     : "=r"(old) : "l"(&g_tick), "r"((unsigned)(gridDim.x - 1))
                     : "memory");
        is_last = (old == gridDim.x - 1) ? 1u : 0u;
    }
    __syncthreads();
    if (is_last) {
        int t = threadIdx.x;
        double v = 0.0;
#pragma unroll
        for (int k = 0; k < 4; k++) {
            int idx = t * 4 + k;
            v += (double)g_num[idx] - (double)g_den[idx];
        }
#pragma unroll
        for (int ofs = 16; ofs; ofs >>= 1) v += __shfl_xor_sync(0xffffffffu, v, ofs);
        if (j == 0) dpart[warp] = v;
        __syncthreads();
        if (t == 0) {
            double tot = dpart[0] + dpart[1] + dpart[2] + dpart[3];
            out[0] = (float)(tot * (1.0 / (double)BB));
        }
    }
}

// ---------------------------------------------------------------------------
extern "C" void kernel_launch(void* const* d_in, const int* in_sizes, int n_in,
                              void* d_out, int out_size)
{
    const float* em     = (const float*)d_in[0];
    const int*   tags   = (const int*)d_in[1];
    const int*   mask   = (const int*)d_in[2];
    const float* startT = (const float*)d_in[3];
    const float* endT   = (const float*)d_in[4];
    const float* trans  = (const float*)d_in[5];

    crf_fused<<<BB / 2, 128>>>(em, tags, mask, trans, startT, endT, (float*)d_out);
}